// round 6
// baseline (speedup 1.0000x reference)
#include <cuda_runtime.h>
#include <math.h>

#define Bq   4
#define Tq   2048
#define Cq   1024
#define FFNq 4096
#define Mq   (Bq * Tq)      // 8192
#define MCq  (Mq * Cq)      // 8,388,608 floats per C-buffer

// Scratch pool: 7 [M,C] buffers + 1 [M,FFN] buffer (reused across phases).
__device__ float g_pool[7 * MCq + Mq * FFNq];

// ---------------- LayerNorm: one block per (b,t) row, 256 threads ----------------
__global__ __launch_bounds__(256) void ln_kernel(
    const float* __restrict__ x, const float* __restrict__ w,
    const float* __restrict__ b, float* __restrict__ out)
{
    int row = blockIdx.x;
    int tid = threadIdx.x;
    float4 v = ((const float4*)(x + (size_t)row * Cq))[tid];
    float s  = v.x + v.y + v.z + v.w;
    float ss = v.x*v.x + v.y*v.y + v.z*v.z + v.w*v.w;
    #pragma unroll
    for (int o = 16; o > 0; o >>= 1) {
        s  += __shfl_xor_sync(0xffffffffu, s, o);
        ss += __shfl_xor_sync(0xffffffffu, ss, o);
    }
    __shared__ float sm0[8], sm1[8];
    int wid = tid >> 5, lane = tid & 31;
    if (lane == 0) { sm0[wid] = s; sm1[wid] = ss; }
    __syncthreads();
    float st = 0.f, sst = 0.f;
    #pragma unroll
    for (int i = 0; i < 8; i++) { st += sm0[i]; sst += sm1[i]; }
    float mean = st * (1.0f / Cq);
    float var  = sst * (1.0f / Cq) - mean * mean;
    float rstd = rsqrtf(var + 1e-5f);
    float4 wv = ((const float4*)w)[tid];
    float4 bv = ((const float4*)b)[tid];
    float4 o;
    o.x = (v.x - mean) * rstd * wv.x + bv.x;
    o.y = (v.y - mean) * rstd * wv.y + bv.y;
    o.z = (v.z - mean) * rstd * wv.z + bv.z;
    o.w = (v.w - mean) * rstd * wv.w + bv.w;
    ((float4*)(out + (size_t)row * Cq))[tid] = o;
}

// ---------------- token-shift mix, 3 outputs (TimeMix) ----------------
__global__ __launch_bounds__(256) void mix3_kernel(
    const float* __restrict__ h,
    const float* __restrict__ mk, const float* __restrict__ mv, const float* __restrict__ mr,
    float* __restrict__ xk, float* __restrict__ xv, float* __restrict__ xr)
{
    int row = blockIdx.x;
    int t   = row % Tq;
    int tid = threadIdx.x;
    float4 hv = ((const float4*)(h + (size_t)row * Cq))[tid];
    float4 hp = (t == 0) ? make_float4(0.f, 0.f, 0.f, 0.f)
                         : ((const float4*)(h + (size_t)(row - 1) * Cq))[tid];
    float4 k4 = ((const float4*)mk)[tid];
    float4 v4 = ((const float4*)mv)[tid];
    float4 r4 = ((const float4*)mr)[tid];
    float4 ok, ov, orr;
    ok.x  = hp.x + k4.x * (hv.x - hp.x); ok.y  = hp.y + k4.y * (hv.y - hp.y);
    ok.z  = hp.z + k4.z * (hv.z - hp.z); ok.w  = hp.w + k4.w * (hv.w - hp.w);
    ov.x  = hp.x + v4.x * (hv.x - hp.x); ov.y  = hp.y + v4.y * (hv.y - hp.y);
    ov.z  = hp.z + v4.z * (hv.z - hp.z); ov.w  = hp.w + v4.w * (hv.w - hp.w);
    orr.x = hp.x + r4.x * (hv.x - hp.x); orr.y = hp.y + r4.y * (hv.y - hp.y);
    orr.z = hp.z + r4.z * (hv.z - hp.z); orr.w = hp.w + r4.w * (hv.w - hp.w);
    ((float4*)(xk + (size_t)row * Cq))[tid] = ok;
    ((float4*)(xv + (size_t)row * Cq))[tid] = ov;
    ((float4*)(xr + (size_t)row * Cq))[tid] = orr;
}

// ---------------- token-shift mix, 2 outputs (ChannelMix) ----------------
__global__ __launch_bounds__(256) void mix2_kernel(
    const float* __restrict__ h,
    const float* __restrict__ mk, const float* __restrict__ mr,
    float* __restrict__ xk, float* __restrict__ xr)
{
    int row = blockIdx.x;
    int t   = row % Tq;
    int tid = threadIdx.x;
    float4 hv = ((const float4*)(h + (size_t)row * Cq))[tid];
    float4 hp = (t == 0) ? make_float4(0.f, 0.f, 0.f, 0.f)
                         : ((const float4*)(h + (size_t)(row - 1) * Cq))[tid];
    float4 k4 = ((const float4*)mk)[tid];
    float4 r4 = ((const float4*)mr)[tid];
    float4 ok, orr;
    ok.x  = hp.x + k4.x * (hv.x - hp.x); ok.y  = hp.y + k4.y * (hv.y - hp.y);
    ok.z  = hp.z + k4.z * (hv.z - hp.z); ok.w  = hp.w + k4.w * (hv.w - hp.w);
    orr.x = hp.x + r4.x * (hv.x - hp.x); orr.y = hp.y + r4.y * (hv.y - hp.y);
    orr.z = hp.z + r4.z * (hv.z - hp.z); orr.w = hp.w + r4.w * (hv.w - hp.w);
    ((float4*)(xk + (size_t)row * Cq))[tid] = ok;
    ((float4*)(xr + (size_t)row * Cq))[tid] = orr;
}

// ---------------- WKV recurrence: one thread per (b,c) channel ----------------
__global__ __launch_bounds__(128) void wkv_kernel(
    const float* __restrict__ k, const float* __restrict__ v, const float* __restrict__ r,
    const float* __restrict__ decay, const float* __restrict__ first,
    float* __restrict__ out)
{
    int idx = blockIdx.x * blockDim.x + threadIdx.x;   // 0 .. B*C-1
    int b = idx / Cq, c = idx % Cq;
    float w = -expf(decay[c]);
    float u = first[c];
    float aa = 0.f, bb = 0.f, pp = -1e38f;
    size_t base = (size_t)b * Tq * Cq + c;
    for (int t = 0; t < Tq; t++) {
        size_t off = base + (size_t)t * Cq;
        float kk = k[off], vv = v[off], rr = r[off];
        float ww = u + kk;
        float p  = fmaxf(pp, ww);
        float e1 = expf(pp - p), e2 = expf(ww - p);
        float o  = (e1 * aa + e2 * vv) / (e1 * bb + e2);
        out[off] = o * (1.f / (1.f + expf(-rr)));       // sigmoid(r) * wkv
        float ww2 = pp + w;
        float p2  = fmaxf(ww2, kk);
        float e1b = expf(ww2 - p2), e2b = expf(kk - p2);
        aa = e1b * aa + e2b * vv;
        bb = e1b * bb + e2b;
        pp = p2;
    }
}

// ---------------- fp32 NT GEMM, double-buffered smem ----------------
// C[m,n] = op( sum_k A[m,k]*W[n,k] )
// OP: 0 none, 1 relu^2, 2 sigmoid, 3 resid+acc, 4 resid+gate*acc
template<int OP>
__global__ __launch_bounds__(256) void sgemm_nt(
    const float* __restrict__ A, const float* __restrict__ Bw, float* __restrict__ Cmat,
    const float* __restrict__ resid, const float* __restrict__ gate,
    int M, int N, int K)
{
    __shared__ float As[2][8][132];
    __shared__ float Bs[2][8][132];
    int tid  = threadIdx.x;
    int bm   = blockIdx.y * 128, bn = blockIdx.x * 128;
    int lrow = tid >> 1;             // 0..127
    int lcol = (tid & 1) << 2;       // 0 or 4
    int tx   = tid & 15, ty = tid >> 4;
    float acc[8][8];
    #pragma unroll
    for (int i = 0; i < 8; i++)
        #pragma unroll
        for (int j = 0; j < 8; j++) acc[i][j] = 0.f;

    const float* Ap = A  + (size_t)(bm + lrow) * K + lcol;
    const float* Bp = Bw + (size_t)(bn + lrow) * K + lcol;

    // prologue: fetch tile 0
    float4 av = *(const float4*)(Ap);
    float4 bv = *(const float4*)(Bp);

    int buf = 0;
    for (int k0 = 0; k0 < K; k0 += 8) {
        As[buf][lcol + 0][lrow] = av.x; As[buf][lcol + 1][lrow] = av.y;
        As[buf][lcol + 2][lrow] = av.z; As[buf][lcol + 3][lrow] = av.w;
        Bs[buf][lcol + 0][lrow] = bv.x; Bs[buf][lcol + 1][lrow] = bv.y;
        Bs[buf][lcol + 2][lrow] = bv.z; Bs[buf][lcol + 3][lrow] = bv.w;
        __syncthreads();
        if (k0 + 8 < K) {
            av = *(const float4*)(Ap + k0 + 8);
            bv = *(const float4*)(Bp + k0 + 8);
        }
        #pragma unroll
        for (int kk = 0; kk < 8; kk++) {
            float a[8], b[8];
            *(float4*)(a)     = *(const float4*)&As[buf][kk][ty * 4];
            *(float4*)(a + 4) = *(const float4*)&As[buf][kk][64 + ty * 4];
            *(float4*)(b)     = *(const float4*)&Bs[buf][kk][tx * 4];
            *(float4*)(b + 4) = *(const float4*)&Bs[buf][kk][64 + tx * 4];
            #pragma unroll
            for (int i = 0; i < 8; i++)
                #pragma unroll
                for (int j = 0; j < 8; j++)
                    acc[i][j] = fmaf(a[i], b[j], acc[i][j]);
        }
        buf ^= 1;
    }

    #pragma unroll
    for (int i = 0; i < 8; i++) {
        int row = bm + ((i < 4) ? (ty * 4 + i) : (64 + ty * 4 + (i - 4)));
        #pragma unroll
        for (int jh = 0; jh < 2; jh++) {
            int col = bn + (jh ? (64 + tx * 4) : (tx * 4));
            size_t o = (size_t)row * N + col;
            float vals[4];
            #pragma unroll
            for (int j = 0; j < 4; j++) {
                float acv = acc[i][jh * 4 + j];
                if (OP == 1)      { float t = fmaxf(acv, 0.f); vals[j] = t * t; }
                else if (OP == 2) { vals[j] = 1.f / (1.f + expf(-acv)); }
                else if (OP == 3) { vals[j] = resid[o + j] + acv; }
                else if (OP == 4) { vals[j] = resid[o + j] + gate[o + j] * acv; }
                else              { vals[j] = acv; }
            }
            float4 rv; rv.x = vals[0]; rv.y = vals[1]; rv.z = vals[2]; rv.w = vals[3];
            *(float4*)&Cmat[o] = rv;
        }
    }
}

// ---------------- host-side orchestration ----------------
extern "C" void kernel_launch(void* const* d_in, const int* in_sizes, int n_in,
                              void* d_out, int out_size)
{
    const float* x          = (const float*)d_in[0];
    const float* ln1_w      = (const float*)d_in[1];
    const float* ln1_b      = (const float*)d_in[2];
    const float* ln2_w      = (const float*)d_in[3];
    const float* ln2_b      = (const float*)d_in[4];
    const float* time_decay = (const float*)d_in[5];
    const float* time_first = (const float*)d_in[6];
    const float* tmk        = (const float*)d_in[7];
    const float* tmv        = (const float*)d_in[8];
    const float* tmr        = (const float*)d_in[9];
    const float* att_kw     = (const float*)d_in[10];
    const float* att_vw     = (const float*)d_in[11];
    const float* att_rw     = (const float*)d_in[12];
    const float* att_ow     = (const float*)d_in[13];
    const float* f_tmk      = (const float*)d_in[14];
    const float* f_tmr      = (const float*)d_in[15];
    const float* f_kw       = (const float*)d_in[16];
    const float* f_rw       = (const float*)d_in[17];
    const float* f_vw       = (const float*)d_in[18];
    float* out = (float*)d_out;

    float* pool = nullptr;
    cudaGetSymbolAddress((void**)&pool, g_pool);
    float* b0 = pool;                 // h (both phases)
    float* b1 = pool + 1 * (size_t)MCq;
    float* b2 = pool + 2 * (size_t)MCq;
    float* b3 = pool + 3 * (size_t)MCq;
    float* b4 = pool + 4 * (size_t)MCq;
    float* b5 = pool + 5 * (size_t)MCq;
    float* b6 = pool + 6 * (size_t)MCq;
    float* bf = pool + 7 * (size_t)MCq;   // [M, FFN]

    dim3 gC(Cq / 128, Mq / 128);     // (8, 64)
    dim3 gF(FFNq / 128, Mq / 128);   // (32, 64)

    // ---- TimeMix ----
    ln_kernel  <<<Mq, 256>>>(x, ln1_w, ln1_b, b0);                       // h = ln1(x)
    mix3_kernel<<<Mq, 256>>>(b0, tmk, tmv, tmr, b1, b2, b3);             // xk,xv,xr
    sgemm_nt<0><<<gC, 256>>>(b1, att_kw, b4, nullptr, nullptr, Mq, Cq, Cq);   // k
    sgemm_nt<0><<<gC, 256>>>(b2, att_vw, b5, nullptr, nullptr, Mq, Cq, Cq);   // v
    sgemm_nt<0><<<gC, 256>>>(b3, att_rw, b6, nullptr, nullptr, Mq, Cq, Cq);   // r
    wkv_kernel <<<(Bq * Cq) / 128, 128>>>(b4, b5, b6, time_decay, time_first, b1); // rwkv (reuse xk)
    sgemm_nt<3><<<gC, 256>>>(b1, att_ow, b2, x, nullptr, Mq, Cq, Cq);    // y = x + rwkv@ow (reuse xv)

    // ---- ChannelMix ----
    ln_kernel  <<<Mq, 256>>>(b2, ln2_w, ln2_b, b0);                      // h = ln2(y)
    mix2_kernel<<<Mq, 256>>>(b0, f_tmk, f_tmr, b3, b4);                  // xk2 (b3), xr2 (b4)
    sgemm_nt<1><<<gF, 256>>>(b3, f_kw, bf, nullptr, nullptr, Mq, FFNq, Cq);   // kk = relu(..)^2
    sgemm_nt<2><<<gC, 256>>>(b4, f_rw, b5, nullptr, nullptr, Mq, Cq, Cq);     // s = sigmoid(..)
    sgemm_nt<4><<<gC, 256>>>(bf, f_vw, out, b2, b5, Mq, Cq, FFNq);       // out = y + s * (kk@vw)
}

// round 9
// speedup vs baseline: 2.3220x; 2.3220x over previous
#include <cuda_runtime.h>
#include <math.h>
#include <stdint.h>

#define Bq   4
#define Tq   2048
#define Cq   1024
#define FFNq 4096
#define Mq   (Bq * Tq)      // 8192
#define MCq  (Mq * Cq)      // floats per [M,C] buffer

// Scratch pool: 7 [M,C] buffers + 1 [M,FFN] buffer (reused across phases).
__device__ float g_pool[7 * MCq + Mq * FFNq];

// ======================= helpers =======================
__device__ __forceinline__ uint32_t smem_u32(const void* p) {
    uint32_t a;
    asm("{ .reg .u64 t; cvta.to.shared.u64 t, %1; cvt.u32.u64 %0, t; }" : "=r"(a) : "l"(p));
    return a;
}
__device__ __forceinline__ void cp_async16(uint32_t dst, const void* src) {
    asm volatile("cp.async.cg.shared.global [%0], [%1], 16;" :: "r"(dst), "l"(src));
}
#define CP_COMMIT() asm volatile("cp.async.commit_group;" ::: "memory")
#define CP_WAIT1()  asm volatile("cp.async.wait_group 1;" ::: "memory")
#define CP_WAIT0()  asm volatile("cp.async.wait_group 0;" ::: "memory")

// mma.sync m16n8k8 TF32 (fp32 bits fed directly; HW uses top 19 bits)
__device__ __forceinline__ void mma_tf32(float* d, const uint32_t* a, const uint32_t* b) {
    asm volatile(
        "mma.sync.aligned.m16n8k8.row.col.f32.tf32.tf32.f32 "
        "{%0,%1,%2,%3}, {%4,%5,%6,%7}, {%8,%9}, {%0,%1,%2,%3};"
        : "+f"(d[0]), "+f"(d[1]), "+f"(d[2]), "+f"(d[3])
        : "r"(a[0]), "r"(a[1]), "r"(a[2]), "r"(a[3]), "r"(b[0]), "r"(b[1]));
}

// ======================= TF32 mma.sync GEMM =======================
// C[m,n] = op( sum_k A[m,k] * Bw[n,k] ),  M%128==0, N%128==0, K%32==0.
// OP: 0 none, 1 relu^2, 2 sigmoid, 3 resid+acc, 4 resid+gate*acc
// SMEM: A[2][128][36], B[2][128][36] floats (stride 36: conflict-free LDGSTS + LDS)
#define LDS_STRIDE 36
#define BUF_FLOATS (128 * LDS_STRIDE)   // 4608

template<int OP>
__global__ __launch_bounds__(256, 2) void gemm_tc(
    const float* __restrict__ A, const float* __restrict__ Bw, float* __restrict__ Cmat,
    const float* __restrict__ resid, const float* __restrict__ gate,
    int M, int N, int K)
{
    extern __shared__ __align__(16) float smf[];
    float* Asm = smf;                       // [2][4608]
    float* Bsm = smf + 2 * BUF_FLOATS;      // [2][4608]
    uint32_t sb = smem_u32(smf);

    int tid = threadIdx.x;
    int lane = tid & 31, wid = tid >> 5;
    int g = lane >> 2, t = lane & 3;        // groupID, thread-in-group
    int warp_m = wid >> 2, warp_n = wid & 3; // 2 x 4 warps
    int m0 = warp_m * 64, n0 = warp_n * 32; // warp tile origin in CTA tile

    int bm = blockIdx.y * 128, bn = blockIdx.x * 128;
    const float* Abase = A  + (size_t)bm * K;
    const float* Bbase = Bw + (size_t)bn * K;

    // per-thread staging assignment: 4 float4 per matrix per chunk
    // idx = tid + s*256 ; row = idx>>3 ; c4 = idx&7  (8 float4 per 32-float row)
    float acc[4][4][4];
    #pragma unroll
    for (int mi = 0; mi < 4; mi++)
        #pragma unroll
        for (int ni = 0; ni < 4; ni++)
            #pragma unroll
            for (int q = 0; q < 4; q++) acc[mi][ni][q] = 0.f;

    int nk = K >> 5;

    // prefetch chunk 0 -> buf 0
    {
        uint32_t asb = sb;                              // A buf0
        uint32_t bsb = sb + 2 * BUF_FLOATS * 4;         // B buf0
        #pragma unroll
        for (int s = 0; s < 4; s++) {
            int idx = tid + s * 256;
            int row = idx >> 3, c4 = idx & 7;
            uint32_t doff = (uint32_t)(row * LDS_STRIDE + c4 * 4) * 4;
            cp_async16(asb + doff, Abase + (size_t)row * K + c4 * 4);
            cp_async16(bsb + doff, Bbase + (size_t)row * K + c4 * 4);
        }
        CP_COMMIT();
    }

    for (int i = 0; i < nk; i++) {
        // prefetch next chunk into other buffer
        if (i + 1 < nk) {
            int nb = (i + 1) & 1;
            int k0 = (i + 1) << 5;
            uint32_t asb = sb + (uint32_t)nb * BUF_FLOATS * 4;
            uint32_t bsb = sb + (uint32_t)(2 + nb) * BUF_FLOATS * 4;
            #pragma unroll
            for (int s = 0; s < 4; s++) {
                int idx = tid + s * 256;
                int row = idx >> 3, c4 = idx & 7;
                uint32_t doff = (uint32_t)(row * LDS_STRIDE + c4 * 4) * 4;
                cp_async16(asb + doff, Abase + (size_t)row * K + k0 + c4 * 4);
                cp_async16(bsb + doff, Bbase + (size_t)row * K + k0 + c4 * 4);
            }
            CP_COMMIT();
            CP_WAIT1();
        } else {
            CP_WAIT0();
        }
        __syncthreads();

        const float* As_ = Asm + (i & 1) * BUF_FLOATS;
        const float* Bs_ = Bsm + (i & 1) * BUF_FLOATS;

        #pragma unroll
        for (int ks = 0; ks < 4; ks++) {
            int k = ks * 8;
            uint32_t af[4][4], bf[4][2];
            #pragma unroll
            for (int mi = 0; mi < 4; mi++) {
                int base = (m0 + mi * 16 + g) * LDS_STRIDE + k + t;
                af[mi][0] = __float_as_uint(As_[base]);
                af[mi][1] = __float_as_uint(As_[base + 8 * LDS_STRIDE]);
                af[mi][2] = __float_as_uint(As_[base + 4]);
                af[mi][3] = __float_as_uint(As_[base + 8 * LDS_STRIDE + 4]);
            }
            #pragma unroll
            for (int ni = 0; ni < 4; ni++) {
                int base = (n0 + ni * 8 + g) * LDS_STRIDE + k + t;
                bf[ni][0] = __float_as_uint(Bs_[base]);
                bf[ni][1] = __float_as_uint(Bs_[base + 4]);
            }
            #pragma unroll
            for (int mi = 0; mi < 4; mi++)
                #pragma unroll
                for (int ni = 0; ni < 4; ni++)
                    mma_tf32(acc[mi][ni], af[mi], bf[ni]);
        }
        __syncthreads();
    }

    // ---- epilogue ----
    #pragma unroll
    for (int mi = 0; mi < 4; mi++) {
        #pragma unroll
        for (int half = 0; half < 2; half++) {       // c0,c1 then c2,c3 (+8 rows)
            int row = bm + warp_m * 64 + mi * 16 + g + half * 8;
            #pragma unroll
            for (int ni = 0; ni < 4; ni++) {
                int col = bn + warp_n * 32 + ni * 8 + t * 2;
                size_t o = (size_t)row * N + col;
                float c0 = acc[mi][ni][half * 2 + 0];
                float c1 = acc[mi][ni][half * 2 + 1];
                float v0, v1;
                if (OP == 1) {
                    float t0 = fmaxf(c0, 0.f), t1 = fmaxf(c1, 0.f);
                    v0 = t0 * t0; v1 = t1 * t1;
                } else if (OP == 2) {
                    v0 = 1.f / (1.f + expf(-c0)); v1 = 1.f / (1.f + expf(-c1));
                } else if (OP == 3) {
                    float2 rv = *(const float2*)&resid[o];
                    v0 = rv.x + c0; v1 = rv.y + c1;
                } else if (OP == 4) {
                    float2 rv = *(const float2*)&resid[o];
                    float2 gv = *(const float2*)&gate[o];
                    v0 = rv.x + gv.x * c0; v1 = rv.y + gv.y * c1;
                } else {
                    v0 = c0; v1 = c1;
                }
                float2 w2; w2.x = v0; w2.y = v1;
                *(float2*)&Cmat[o] = w2;
            }
        }
    }
}

// ======================= elementwise kernels =======================
__global__ __launch_bounds__(256) void ln_kernel(
    const float* __restrict__ x, const float* __restrict__ w,
    const float* __restrict__ b, float* __restrict__ out)
{
    int row = blockIdx.x;
    int tid = threadIdx.x;
    float4 v = ((const float4*)(x + (size_t)row * Cq))[tid];
    float s  = v.x + v.y + v.z + v.w;
    float ss = v.x*v.x + v.y*v.y + v.z*v.z + v.w*v.w;
    #pragma unroll
    for (int o = 16; o > 0; o >>= 1) {
        s  += __shfl_xor_sync(0xffffffffu, s, o);
        ss += __shfl_xor_sync(0xffffffffu, ss, o);
    }
    __shared__ float sm0[8], sm1[8];
    int wid = tid >> 5, lane = tid & 31;
    if (lane == 0) { sm0[wid] = s; sm1[wid] = ss; }
    __syncthreads();
    float st = 0.f, sst = 0.f;
    #pragma unroll
    for (int i = 0; i < 8; i++) { st += sm0[i]; sst += sm1[i]; }
    float mean = st * (1.0f / Cq);
    float var  = sst * (1.0f / Cq) - mean * mean;
    float rstd = rsqrtf(var + 1e-5f);
    float4 wv = ((const float4*)w)[tid];
    float4 bv = ((const float4*)b)[tid];
    float4 o;
    o.x = (v.x - mean) * rstd * wv.x + bv.x;
    o.y = (v.y - mean) * rstd * wv.y + bv.y;
    o.z = (v.z - mean) * rstd * wv.z + bv.z;
    o.w = (v.w - mean) * rstd * wv.w + bv.w;
    ((float4*)(out + (size_t)row * Cq))[tid] = o;
}

__global__ __launch_bounds__(256) void mix3_kernel(
    const float* __restrict__ h,
    const float* __restrict__ mk, const float* __restrict__ mv, const float* __restrict__ mr,
    float* __restrict__ xk, float* __restrict__ xv, float* __restrict__ xr)
{
    int row = blockIdx.x;
    int t   = row % Tq;
    int tid = threadIdx.x;
    float4 hv = ((const float4*)(h + (size_t)row * Cq))[tid];
    float4 hp = (t == 0) ? make_float4(0.f, 0.f, 0.f, 0.f)
                         : ((const float4*)(h + (size_t)(row - 1) * Cq))[tid];
    float4 k4 = ((const float4*)mk)[tid];
    float4 v4 = ((const float4*)mv)[tid];
    float4 r4 = ((const float4*)mr)[tid];
    float4 ok, ov, orr;
    ok.x  = hp.x + k4.x * (hv.x - hp.x); ok.y  = hp.y + k4.y * (hv.y - hp.y);
    ok.z  = hp.z + k4.z * (hv.z - hp.z); ok.w  = hp.w + k4.w * (hv.w - hp.w);
    ov.x  = hp.x + v4.x * (hv.x - hp.x); ov.y  = hp.y + v4.y * (hv.y - hp.y);
    ov.z  = hp.z + v4.z * (hv.z - hp.z); ov.w  = hp.w + v4.w * (hv.w - hp.w);
    orr.x = hp.x + r4.x * (hv.x - hp.x); orr.y = hp.y + r4.y * (hv.y - hp.y);
    orr.z = hp.z + r4.z * (hv.z - hp.z); orr.w = hp.w + r4.w * (hv.w - hp.w);
    ((float4*)(xk + (size_t)row * Cq))[tid] = ok;
    ((float4*)(xv + (size_t)row * Cq))[tid] = ov;
    ((float4*)(xr + (size_t)row * Cq))[tid] = orr;
}

__global__ __launch_bounds__(256) void mix2_kernel(
    const float* __restrict__ h,
    const float* __restrict__ mk, const float* __restrict__ mr,
    float* __restrict__ xk, float* __restrict__ xr)
{
    int row = blockIdx.x;
    int t   = row % Tq;
    int tid = threadIdx.x;
    float4 hv = ((const float4*)(h + (size_t)row * Cq))[tid];
    float4 hp = (t == 0) ? make_float4(0.f, 0.f, 0.f, 0.f)
                         : ((const float4*)(h + (size_t)(row - 1) * Cq))[tid];
    float4 k4 = ((const float4*)mk)[tid];
    float4 r4 = ((const float4*)mr)[tid];
    float4 ok, orr;
    ok.x  = hp.x + k4.x * (hv.x - hp.x); ok.y  = hp.y + k4.y * (hv.y - hp.y);
    ok.z  = hp.z + k4.z * (hv.z - hp.z); ok.w  = hp.w + k4.w * (hv.w - hp.w);
    orr.x = hp.x + r4.x * (hv.x - hp.x); orr.y = hp.y + r4.y * (hv.y - hp.y);
    orr.z = hp.z + r4.z * (hv.z - hp.z); orr.w = hp.w + r4.w * (hv.w - hp.w);
    ((float4*)(xk + (size_t)row * Cq))[tid] = ok;
    ((float4*)(xr + (size_t)row * Cq))[tid] = orr;
}

// WKV recurrence, software-pipelined loads (prefetch t+1 while computing t)
__global__ __launch_bounds__(128) void wkv_kernel(
    const float* __restrict__ k, const float* __restrict__ v, const float* __restrict__ r,
    const float* __restrict__ decay, const float* __restrict__ first,
    float* __restrict__ out)
{
    int idx = blockIdx.x * blockDim.x + threadIdx.x;   // 0 .. B*C-1
    int b = idx / Cq, c = idx % Cq;
    float w = -expf(decay[c]);
    float u = first[c];
    float aa = 0.f, bb = 0.f, pp = -1e38f;
    size_t base = (size_t)b * Tq * Cq + c;
    float kk = k[base], vv = v[base], rr = r[base];
    for (int t = 0; t < Tq; t++) {
        size_t off = base + (size_t)t * Cq;
        float kn = 0.f, vn = 0.f, rn = 0.f;
        if (t + 1 < Tq) {
            size_t offn = off + Cq;
            kn = k[offn]; vn = v[offn]; rn = r[offn];
        }
        float ww = u + kk;
        float p  = fmaxf(pp, ww);
        float e1 = expf(pp - p), e2 = expf(ww - p);
        float o  = (e1 * aa + e2 * vv) / (e1 * bb + e2);
        out[off] = o * (1.f / (1.f + expf(-rr)));
        float ww2 = pp + w;
        float p2  = fmaxf(ww2, kk);
        float e1b = expf(ww2 - p2), e2b = expf(kk - p2);
        aa = e1b * aa + e2b * vv;
        bb = e1b * bb + e2b;
        pp = p2;
        kk = kn; vv = vn; rr = rn;
    }
}

// ======================= host orchestration =======================
extern "C" void kernel_launch(void* const* d_in, const int* in_sizes, int n_in,
                              void* d_out, int out_size)
{
    const float* x          = (const float*)d_in[0];
    const float* ln1_w      = (const float*)d_in[1];
    const float* ln1_b      = (const float*)d_in[2];
    const float* ln2_w      = (const float*)d_in[3];
    const float* ln2_b      = (const float*)d_in[4];
    const float* time_decay = (const float*)d_in[5];
    const float* time_first = (const float*)d_in[6];
    const float* tmk        = (const float*)d_in[7];
    const float* tmv        = (const float*)d_in[8];
    const float* tmr        = (const float*)d_in[9];
    const float* att_kw     = (const float*)d_in[10];
    const float* att_vw     = (const float*)d_in[11];
    const float* att_rw     = (const float*)d_in[12];
    const float* att_ow     = (const float*)d_in[13];
    const float* f_tmk      = (const float*)d_in[14];
    const float* f_tmr      = (const float*)d_in[15];
    const float* f_kw       = (const float*)d_in[16];
    const float* f_rw       = (const float*)d_in[17];
    const float* f_vw       = (const float*)d_in[18];
    float* out = (float*)d_out;

    float* pool = nullptr;
    cudaGetSymbolAddress((void**)&pool, g_pool);
    float* b0 = pool;
    float* b1 = pool + 1 * (size_t)MCq;
    float* b2 = pool + 2 * (size_t)MCq;
    float* b3 = pool + 3 * (size_t)MCq;
    float* b4 = pool + 4 * (size_t)MCq;
    float* b5 = pool + 5 * (size_t)MCq;
    float* b6 = pool + 6 * (size_t)MCq;
    float* bf = pool + 7 * (size_t)MCq;   // [M, FFN]

    const int SMEM = 4 * BUF_FLOATS * 4;  // 73728 B
    cudaFuncSetAttribute(gemm_tc<0>, cudaFuncAttributeMaxDynamicSharedMemorySize, SMEM);
    cudaFuncSetAttribute(gemm_tc<1>, cudaFuncAttributeMaxDynamicSharedMemorySize, SMEM);
    cudaFuncSetAttribute(gemm_tc<2>, cudaFuncAttributeMaxDynamicSharedMemorySize, SMEM);
    cudaFuncSetAttribute(gemm_tc<3>, cudaFuncAttributeMaxDynamicSharedMemorySize, SMEM);
    cudaFuncSetAttribute(gemm_tc<4>, cudaFuncAttributeMaxDynamicSharedMemorySize, SMEM);

    dim3 gC(Cq / 128, Mq / 128);     // (8, 64)
    dim3 gF(FFNq / 128, Mq / 128);   // (32, 64)

    // ---- TimeMix ----
    ln_kernel  <<<Mq, 256>>>(x, ln1_w, ln1_b, b0);
    mix3_kernel<<<Mq, 256>>>(b0, tmk, tmv, tmr, b1, b2, b3);
    gemm_tc<0><<<gC, 256, SMEM>>>(b1, att_kw, b4, nullptr, nullptr, Mq, Cq, Cq);   // k
    gemm_tc<0><<<gC, 256, SMEM>>>(b2, att_vw, b5, nullptr, nullptr, Mq, Cq, Cq);   // v
    gemm_tc<0><<<gC, 256, SMEM>>>(b3, att_rw, b6, nullptr, nullptr, Mq, Cq, Cq);   // r
    wkv_kernel <<<(Bq * Cq) / 128, 128>>>(b4, b5, b6, time_decay, time_first, b1); // sr*wkv
    gemm_tc<3><<<gC, 256, SMEM>>>(b1, att_ow, b2, x, nullptr, Mq, Cq, Cq);         // y = x + rwkv@ow

    // ---- ChannelMix ----
    ln_kernel  <<<Mq, 256>>>(b2, ln2_w, ln2_b, b0);
    mix2_kernel<<<Mq, 256>>>(b0, f_tmk, f_tmr, b3, b4);
    gemm_tc<1><<<gF, 256, SMEM>>>(b3, f_kw, bf, nullptr, nullptr, Mq, FFNq, Cq);   // kk = relu(..)^2
    gemm_tc<2><<<gC, 256, SMEM>>>(b4, f_rw, b5, nullptr, nullptr, Mq, Cq, Cq);     // s = sigmoid(..)
    gemm_tc<4><<<gC, 256, SMEM>>>(bf, f_vw, out, b2, b5, Mq, Cq, FFNq);            // out = y + s*(kk@vw)
}

// round 12
// speedup vs baseline: 3.3717x; 1.4521x over previous
#include <cuda_runtime.h>
#include <math.h>
#include <stdint.h>

#define Bq   4
#define Tq   2048
#define Cq   1024
#define FFNq 4096
#define Mq   (Bq * Tq)      // 8192
#define MCq  (Mq * Cq)      // floats per [M,C] buffer

// Scratch pool: 7 [M,C] buffers + 1 [M,FFN] buffer (reused across phases).
__device__ float g_pool[7 * MCq + Mq * FFNq];

// ======================= helpers =======================
__device__ __forceinline__ uint32_t smem_u32(const void* p) {
    uint32_t a;
    asm("{ .reg .u64 t; cvta.to.shared.u64 t, %1; cvt.u32.u64 %0, t; }" : "=r"(a) : "l"(p));
    return a;
}
__device__ __forceinline__ void cp_async16(uint32_t dst, const void* src) {
    asm volatile("cp.async.cg.shared.global [%0], [%1], 16;" :: "r"(dst), "l"(src));
}
#define CP_COMMIT() asm volatile("cp.async.commit_group;" ::: "memory")
#define CP_WAIT2()  asm volatile("cp.async.wait_group 2;" ::: "memory")
#define CP_WAIT1()  asm volatile("cp.async.wait_group 1;" ::: "memory")
#define CP_WAIT0()  asm volatile("cp.async.wait_group 0;" ::: "memory")

// mma.sync m16n8k8 TF32 (fp32 bits fed directly; HW uses top 19 bits)
__device__ __forceinline__ void mma_tf32(float* d, const uint32_t* a, const uint32_t* b) {
    asm volatile(
        "mma.sync.aligned.m16n8k8.row.col.f32.tf32.tf32.f32 "
        "{%0,%1,%2,%3}, {%4,%5,%6,%7}, {%8,%9}, {%0,%1,%2,%3};"
        : "+f"(d[0]), "+f"(d[1]), "+f"(d[2]), "+f"(d[3])
        : "r"(a[0]), "r"(a[1]), "r"(a[2]), "r"(a[3]), "r"(b[0]), "r"(b[1]));
}

// ======================= TF32 mma.sync GEMM core =======================
// C[m,n] = op( sum_k A[m,k] * Bw[n,k] ),  N%128==0, K%32==0.
// OP: 0 none, 1 relu^2, 2 sigmoid, 3 resid+acc, 4 resid+gate*acc
// SMEM: 3-stage A[3][128][36] + B[3][128][36] floats.
#define LDS_STRIDE 36
#define BUF_FLOATS (128 * LDS_STRIDE)     // 4608
#define GEMM_SMEM  (6 * BUF_FLOATS * 4)   // 110592 B

template<int OP>
__device__ __forceinline__ void gemm_core(
    const float* __restrict__ A, const float* __restrict__ Bw, float* __restrict__ Cmat,
    const float* __restrict__ resid, const float* __restrict__ gate,
    int N, int K, int bm, int bn, float* smf)
{
    float* Asm = smf;                       // [3][4608]
    float* Bsm = smf + 3 * BUF_FLOATS;      // [3][4608]
    uint32_t sb = smem_u32(smf);

    int tid = threadIdx.x;
    int lane = tid & 31, wid = tid >> 5;
    int g = lane >> 2, t = lane & 3;         // groupID, thread-in-group
    int warp_m = wid >> 2, warp_n = wid & 3; // 2 x 4 warps
    int m0 = warp_m * 64, n0 = warp_n * 32;

    const float* Abase = A  + (size_t)bm * K;
    const float* Bbase = Bw + (size_t)bn * K;

    float acc[4][4][4];
    #pragma unroll
    for (int mi = 0; mi < 4; mi++)
        #pragma unroll
        for (int ni = 0; ni < 4; ni++)
            #pragma unroll
            for (int q = 0; q < 4; q++) acc[mi][ni][q] = 0.f;

    int nk = K >> 5;

    // stage `chunk` into smem slot chunk%3
    auto stage = [&](int chunk) {
        int s = chunk - (chunk / 3) * 3;
        uint32_t asb = sb + (uint32_t)s * BUF_FLOATS * 4;
        uint32_t bsb = sb + (uint32_t)(3 + s) * BUF_FLOATS * 4;
        int k0 = chunk << 5;
        #pragma unroll
        for (int s4 = 0; s4 < 4; s4++) {
            int idx = tid + s4 * 256;
            int row = idx >> 3, c4 = idx & 7;
            uint32_t doff = (uint32_t)(row * LDS_STRIDE + c4 * 4) * 4;
            cp_async16(asb + doff, Abase + (size_t)row * K + k0 + c4 * 4);
            cp_async16(bsb + doff, Bbase + (size_t)row * K + k0 + c4 * 4);
        }
        CP_COMMIT();
    };

    stage(0);
    if (nk > 1) stage(1);

    for (int i = 0; i < nk; i++) {
        if (i + 2 < nk) { stage(i + 2); CP_WAIT2(); }
        else if (i + 1 < nk) { CP_WAIT1(); }
        else { CP_WAIT0(); }
        __syncthreads();

        int s = i - (i / 3) * 3;
        const float* As_ = Asm + s * BUF_FLOATS;
        const float* Bs_ = Bsm + s * BUF_FLOATS;

        #pragma unroll
        for (int ks = 0; ks < 4; ks++) {
            int k = ks * 8;
            uint32_t af[4][4], bf[4][2];
            #pragma unroll
            for (int mi = 0; mi < 4; mi++) {
                int base = (m0 + mi * 16 + g) * LDS_STRIDE + k + t;
                af[mi][0] = __float_as_uint(As_[base]);
                af[mi][1] = __float_as_uint(As_[base + 8 * LDS_STRIDE]);
                af[mi][2] = __float_as_uint(As_[base + 4]);
                af[mi][3] = __float_as_uint(As_[base + 8 * LDS_STRIDE + 4]);
            }
            #pragma unroll
            for (int ni = 0; ni < 4; ni++) {
                int base = (n0 + ni * 8 + g) * LDS_STRIDE + k + t;
                bf[ni][0] = __float_as_uint(Bs_[base]);
                bf[ni][1] = __float_as_uint(Bs_[base + 4]);
            }
            #pragma unroll
            for (int mi = 0; mi < 4; mi++)
                #pragma unroll
                for (int ni = 0; ni < 4; ni++)
                    mma_tf32(acc[mi][ni], af[mi], bf[ni]);
        }
        __syncthreads();
    }

    // ---- epilogue ----
    #pragma unroll
    for (int mi = 0; mi < 4; mi++) {
        #pragma unroll
        for (int half = 0; half < 2; half++) {
            int row = bm + warp_m * 64 + mi * 16 + g + half * 8;
            #pragma unroll
            for (int ni = 0; ni < 4; ni++) {
                int col = bn + warp_n * 32 + ni * 8 + t * 2;
                size_t o = (size_t)row * N + col;
                float c0 = acc[mi][ni][half * 2 + 0];
                float c1 = acc[mi][ni][half * 2 + 1];
                float v0, v1;
                if (OP == 1) {
                    float t0 = fmaxf(c0, 0.f), t1 = fmaxf(c1, 0.f);
                    v0 = t0 * t0; v1 = t1 * t1;
                } else if (OP == 2) {
                    v0 = 1.f / (1.f + expf(-c0)); v1 = 1.f / (1.f + expf(-c1));
                } else if (OP == 3) {
                    float2 rv = *(const float2*)&resid[o];
                    v0 = rv.x + c0; v1 = rv.y + c1;
                } else if (OP == 4) {
                    float2 rv = *(const float2*)&resid[o];
                    float2 gv = *(const float2*)&gate[o];
                    v0 = rv.x + gv.x * c0; v1 = rv.y + gv.y * c1;
                } else {
                    v0 = c0; v1 = c1;
                }
                float2 w2; w2.x = v0; w2.y = v1;
                *(float2*)&Cmat[o] = w2;
            }
        }
    }
}

template<int OP>
__global__ __launch_bounds__(256, 2) void gemm_tc(
    const float* __restrict__ A, const float* __restrict__ Bw, float* __restrict__ Cmat,
    const float* __restrict__ resid, const float* __restrict__ gate,
    int M, int N, int K)
{
    extern __shared__ __align__(16) float smf[];
    gemm_core<OP>(A, Bw, Cmat, resid, gate, N, K,
                  blockIdx.y * 128, blockIdx.x * 128, smf);
}

// z-batched k/v/r GEMM: one launch, blockIdx.z selects (A, W, C) triple
__global__ __launch_bounds__(256, 2) void gemm_kvr(
    const float* __restrict__ A0, const float* __restrict__ A1, const float* __restrict__ A2,
    const float* __restrict__ W0, const float* __restrict__ W1, const float* __restrict__ W2,
    float* __restrict__ C0, float* __restrict__ C1, float* __restrict__ C2,
    int N, int K)
{
    extern __shared__ __align__(16) float smf[];
    const float* A  = (blockIdx.z == 0) ? A0 : (blockIdx.z == 1) ? A1 : A2;
    const float* Bw = (blockIdx.z == 0) ? W0 : (blockIdx.z == 1) ? W1 : W2;
    float*       C  = (blockIdx.z == 0) ? C0 : (blockIdx.z == 1) ? C1 : C2;
    gemm_core<0>(A, Bw, C, nullptr, nullptr, N, K,
                 blockIdx.y * 128, blockIdx.x * 128, smf);
}

// ======================= fused LN + token-shift mix =======================
// Computes h=LN(x_row), hp=LN(x_{row-1}) (0 at t==0), then the lerp mixes.
__device__ __forceinline__ void ln_pair(
    const float* __restrict__ x, int row, int t, int tid,
    const float* __restrict__ w, const float* __restrict__ b,
    float4& h, float4& hp)
{
    float4 v = ((const float4*)(x + (size_t)row * Cq))[tid];
    float4 vp = make_float4(0.f, 0.f, 0.f, 0.f);
    if (t != 0) vp = ((const float4*)(x + (size_t)(row - 1) * Cq))[tid];
    float s   = v.x + v.y + v.z + v.w;
    float ss  = v.x*v.x + v.y*v.y + v.z*v.z + v.w*v.w;
    float sp  = vp.x + vp.y + vp.z + vp.w;
    float ssp = vp.x*vp.x + vp.y*vp.y + vp.z*vp.z + vp.w*vp.w;
    #pragma unroll
    for (int o = 16; o > 0; o >>= 1) {
        s   += __shfl_xor_sync(0xffffffffu, s, o);
        ss  += __shfl_xor_sync(0xffffffffu, ss, o);
        sp  += __shfl_xor_sync(0xffffffffu, sp, o);
        ssp += __shfl_xor_sync(0xffffffffu, ssp, o);
    }
    __shared__ float sm[4][8];
    int wid = tid >> 5, lane = tid & 31;
    if (lane == 0) { sm[0][wid] = s; sm[1][wid] = ss; sm[2][wid] = sp; sm[3][wid] = ssp; }
    __syncthreads();
    float st = 0.f, sst = 0.f, spt = 0.f, sspt = 0.f;
    #pragma unroll
    for (int i = 0; i < 8; i++) { st += sm[0][i]; sst += sm[1][i]; spt += sm[2][i]; sspt += sm[3][i]; }
    float mean  = st * (1.0f / Cq);
    float var   = sst * (1.0f / Cq) - mean * mean;
    float rstd  = rsqrtf(var + 1e-5f);
    float meanp = spt * (1.0f / Cq);
    float varp  = sspt * (1.0f / Cq) - meanp * meanp;
    float rstdp = rsqrtf(varp + 1e-5f);
    float4 wv = ((const float4*)w)[tid];
    float4 bv = ((const float4*)b)[tid];
    h.x = (v.x - mean) * rstd * wv.x + bv.x;
    h.y = (v.y - mean) * rstd * wv.y + bv.y;
    h.z = (v.z - mean) * rstd * wv.z + bv.z;
    h.w = (v.w - mean) * rstd * wv.w + bv.w;
    if (t != 0) {
        hp.x = (vp.x - meanp) * rstdp * wv.x + bv.x;
        hp.y = (vp.y - meanp) * rstdp * wv.y + bv.y;
        hp.z = (vp.z - meanp) * rstdp * wv.z + bv.z;
        hp.w = (vp.w - meanp) * rstdp * wv.w + bv.w;
    } else {
        hp = make_float4(0.f, 0.f, 0.f, 0.f);
    }
}

__global__ __launch_bounds__(256) void lnmix3_kernel(
    const float* __restrict__ x, const float* __restrict__ w, const float* __restrict__ b,
    const float* __restrict__ mk, const float* __restrict__ mv, const float* __restrict__ mr,
    float* __restrict__ xk, float* __restrict__ xv, float* __restrict__ xr)
{
    int row = blockIdx.x, t = row % Tq, tid = threadIdx.x;
    float4 h, hp;
    ln_pair(x, row, t, tid, w, b, h, hp);
    float4 k4 = ((const float4*)mk)[tid];
    float4 v4 = ((const float4*)mv)[tid];
    float4 r4 = ((const float4*)mr)[tid];
    float4 ok, ov, orr;
    ok.x  = hp.x + k4.x * (h.x - hp.x); ok.y  = hp.y + k4.y * (h.y - hp.y);
    ok.z  = hp.z + k4.z * (h.z - hp.z); ok.w  = hp.w + k4.w * (h.w - hp.w);
    ov.x  = hp.x + v4.x * (h.x - hp.x); ov.y  = hp.y + v4.y * (h.y - hp.y);
    ov.z  = hp.z + v4.z * (h.z - hp.z); ov.w  = hp.w + v4.w * (h.w - hp.w);
    orr.x = hp.x + r4.x * (h.x - hp.x); orr.y = hp.y + r4.y * (h.y - hp.y);
    orr.z = hp.z + r4.z * (h.z - hp.z); orr.w = hp.w + r4.w * (h.w - hp.w);
    ((float4*)(xk + (size_t)row * Cq))[tid] = ok;
    ((float4*)(xv + (size_t)row * Cq))[tid] = ov;
    ((float4*)(xr + (size_t)row * Cq))[tid] = orr;
}

__global__ __launch_bounds__(256) void lnmix2_kernel(
    const float* __restrict__ x, const float* __restrict__ w, const float* __restrict__ b,
    const float* __restrict__ mk, const float* __restrict__ mr,
    float* __restrict__ xk, float* __restrict__ xr)
{
    int row = blockIdx.x, t = row % Tq, tid = threadIdx.x;
    float4 h, hp;
    ln_pair(x, row, t, tid, w, b, h, hp);
    float4 k4 = ((const float4*)mk)[tid];
    float4 r4 = ((const float4*)mr)[tid];
    float4 ok, orr;
    ok.x  = hp.x + k4.x * (h.x - hp.x); ok.y  = hp.y + k4.y * (h.y - hp.y);
    ok.z  = hp.z + k4.z * (h.z - hp.z); ok.w  = hp.w + k4.w * (h.w - hp.w);
    orr.x = hp.x + r4.x * (h.x - hp.x); orr.y = hp.y + r4.y * (h.y - hp.y);
    orr.z = hp.z + r4.z * (h.z - hp.z); orr.w = hp.w + r4.w * (h.w - hp.w);
    ((float4*)(xk + (size_t)row * Cq))[tid] = ok;
    ((float4*)(xr + (size_t)row * Cq))[tid] = orr;
}

// ======================= WKV recurrence =======================
// Block-of-8 double-buffered register prefetch: load block j+1 while the
// serial exp-chain of block j runs (hides L2 latency).
#define WSTEP 8
__device__ __forceinline__ void wkv_load8(
    const float* __restrict__ k, const float* __restrict__ v, const float* __restrict__ r,
    size_t base, int blk, float* kb, float* vb, float* rb)
{
    size_t o = base + (size_t)blk * WSTEP * Cq;
    #pragma unroll
    for (int j = 0; j < WSTEP; j++) {
        kb[j] = k[o]; vb[j] = v[o]; rb[j] = r[o];
        o += Cq;
    }
}
__device__ __forceinline__ void wkv_comp8(
    float* __restrict__ out, size_t base, int blk,
    const float* kb, const float* vb, const float* rb,
    float w, float u, float& aa, float& bb, float& pp)
{
    size_t o = base + (size_t)blk * WSTEP * Cq;
    #pragma unroll
    for (int j = 0; j < WSTEP; j++) {
        float kk = kb[j], vv = vb[j], rr = rb[j];
        float ww = u + kk;
        float p  = fmaxf(pp, ww);
        float e1 = expf(pp - p), e2 = expf(ww - p);
        float ov = (e1 * aa + e2 * vv) / (e1 * bb + e2);
        out[o] = ov * (1.f / (1.f + expf(-rr)));
        float ww2 = pp + w;
        float p2  = fmaxf(ww2, kk);
        float e1b = expf(ww2 - p2), e2b = expf(kk - p2);
        aa = e1b * aa + e2b * vv;
        bb = e1b * bb + e2b;
        pp = p2;
        o += Cq;
    }
}

__global__ __launch_bounds__(128) void wkv_kernel(
    const float* __restrict__ k, const float* __restrict__ v, const float* __restrict__ r,
    const float* __restrict__ decay, const float* __restrict__ first,
    float* __restrict__ out)
{
    int idx = blockIdx.x * blockDim.x + threadIdx.x;   // 0 .. B*C-1
    int b = idx / Cq, c = idx % Cq;
    float w = -expf(decay[c]);
    float u = first[c];
    float aa = 0.f, bb = 0.f, pp = -1e38f;
    size_t base = (size_t)b * Tq * Cq + c;

    const int NB = Tq / WSTEP;     // 256 (even)
    float kb0[WSTEP], vb0[WSTEP], rb0[WSTEP];
    float kb1[WSTEP], vb1[WSTEP], rb1[WSTEP];
    wkv_load8(k, v, r, base, 0, kb0, vb0, rb0);
    for (int blk = 0; blk < NB; blk += 2) {
        wkv_load8(k, v, r, base, blk + 1, kb1, vb1, rb1);
        wkv_comp8(out, base, blk, kb0, vb0, rb0, w, u, aa, bb, pp);
        if (blk + 2 < NB) wkv_load8(k, v, r, base, blk + 2, kb0, vb0, rb0);
        wkv_comp8(out, base, blk + 1, kb1, vb1, rb1, w, u, aa, bb, pp);
    }
}

// ======================= host orchestration =======================
extern "C" void kernel_launch(void* const* d_in, const int* in_sizes, int n_in,
                              void* d_out, int out_size)
{
    const float* x          = (const float*)d_in[0];
    const float* ln1_w      = (const float*)d_in[1];
    const float* ln1_b      = (const float*)d_in[2];
    const float* ln2_w      = (const float*)d_in[3];
    const float* ln2_b      = (const float*)d_in[4];
    const float* time_decay = (const float*)d_in[5];
    const float* time_first = (const float*)d_in[6];
    const float* tmk        = (const float*)d_in[7];
    const float* tmv        = (const float*)d_in[8];
    const float* tmr        = (const float*)d_in[9];
    const float* att_kw     = (const float*)d_in[10];
    const float* att_vw     = (const float*)d_in[11];
    const float* att_rw     = (const float*)d_in[12];
    const float* att_ow     = (const float*)d_in[13];
    const float* f_tmk      = (const float*)d_in[14];
    const float* f_tmr      = (const float*)d_in[15];
    const float* f_kw       = (const float*)d_in[16];
    const float* f_rw       = (const float*)d_in[17];
    const float* f_vw       = (const float*)d_in[18];
    float* out = (float*)d_out;

    float* pool = nullptr;
    cudaGetSymbolAddress((void**)&pool, g_pool);
    float* b1 = pool + 1 * (size_t)MCq;
    float* b2 = pool + 2 * (size_t)MCq;
    float* b3 = pool + 3 * (size_t)MCq;
    float* b4 = pool + 4 * (size_t)MCq;
    float* b5 = pool + 5 * (size_t)MCq;
    float* b6 = pool + 6 * (size_t)MCq;
    float* bf = pool + 7 * (size_t)MCq;   // [M, FFN]

    cudaFuncSetAttribute(gemm_tc<1>, cudaFuncAttributeMaxDynamicSharedMemorySize, GEMM_SMEM);
    cudaFuncSetAttribute(gemm_tc<2>, cudaFuncAttributeMaxDynamicSharedMemorySize, GEMM_SMEM);
    cudaFuncSetAttribute(gemm_tc<3>, cudaFuncAttributeMaxDynamicSharedMemorySize, GEMM_SMEM);
    cudaFuncSetAttribute(gemm_tc<4>, cudaFuncAttributeMaxDynamicSharedMemorySize, GEMM_SMEM);
    cudaFuncSetAttribute(gemm_kvr,   cudaFuncAttributeMaxDynamicSharedMemorySize, GEMM_SMEM);

    dim3 gC(Cq / 128, Mq / 128);        // (8, 64)
    dim3 gF(FFNq / 128, Mq / 128);      // (32, 64)
    dim3 gKVR(Cq / 128, Mq / 128, 3);   // (8, 64, 3)

    // ---- TimeMix ----
    lnmix3_kernel<<<Mq, 256>>>(x, ln1_w, ln1_b, tmk, tmv, tmr, b1, b2, b3);
    gemm_kvr<<<gKVR, 256, GEMM_SMEM>>>(b1, b2, b3, att_kw, att_vw, att_rw,
                                       b4, b5, b6, Cq, Cq);
    wkv_kernel<<<(Bq * Cq) / 128, 128>>>(b4, b5, b6, time_decay, time_first, b1);
    gemm_tc<3><<<gC, 256, GEMM_SMEM>>>(b1, att_ow, b2, x, nullptr, Mq, Cq, Cq);   // y = x + rwkv@ow

    // ---- ChannelMix ----
    lnmix2_kernel<<<Mq, 256>>>(b2, ln2_w, ln2_b, f_tmk, f_tmr, b3, b4);
    gemm_tc<1><<<gF, 256, GEMM_SMEM>>>(b3, f_kw, bf, nullptr, nullptr, Mq, FFNq, Cq);  // relu^2
    gemm_tc<2><<<gC, 256, GEMM_SMEM>>>(b4, f_rw, b5, nullptr, nullptr, Mq, Cq, Cq);    // sigmoid
    gemm_tc<4><<<gC, 256, GEMM_SMEM>>>(bf, f_vw, out, b2, b5, Mq, Cq, FFNq);           // y + s*(kk@vw)
}

// round 15
// speedup vs baseline: 3.4233x; 1.0153x over previous
#include <cuda_runtime.h>
#include <math.h>
#include <stdint.h>

#define Bq   4
#define Tq   2048
#define Cq   1024
#define FFNq 4096
#define Mq   (Bq * Tq)      // 8192
#define MCq  (Mq * Cq)      // floats per [M,C] buffer

// Scratch pool: 7 [M,C] buffers + 1 [M,FFN] buffer (reused across phases).
__device__ float g_pool[7 * MCq + Mq * FFNq];

// ======================= helpers =======================
__device__ __forceinline__ uint32_t smem_u32(const void* p) {
    uint32_t a;
    asm("{ .reg .u64 t; cvta.to.shared.u64 t, %1; cvt.u32.u64 %0, t; }" : "=r"(a) : "l"(p));
    return a;
}
__device__ __forceinline__ void cp_async16(uint32_t dst, const void* src) {
    asm volatile("cp.async.cg.shared.global [%0], [%1], 16;" :: "r"(dst), "l"(src));
}
#define CP_COMMIT() asm volatile("cp.async.commit_group;" ::: "memory")
#define CP_WAIT2()  asm volatile("cp.async.wait_group 2;" ::: "memory")
#define CP_WAIT1()  asm volatile("cp.async.wait_group 1;" ::: "memory")
#define CP_WAIT0()  asm volatile("cp.async.wait_group 0;" ::: "memory")

// mma.sync m16n8k8 TF32 (fp32 bits fed directly; HW uses top 19 bits)
__device__ __forceinline__ void mma_tf32(float* d, const uint32_t* a, const uint32_t* b) {
    asm volatile(
        "mma.sync.aligned.m16n8k8.row.col.f32.tf32.tf32.f32 "
        "{%0,%1,%2,%3}, {%4,%5,%6,%7}, {%8,%9}, {%0,%1,%2,%3};"
        : "+f"(d[0]), "+f"(d[1]), "+f"(d[2]), "+f"(d[3])
        : "r"(a[0]), "r"(a[1]), "r"(a[2]), "r"(a[3]), "r"(b[0]), "r"(b[1]));
}

// ======================= TF32 mma.sync GEMM core =======================
// 128x128 CTA tile, 128 threads = 4 warps (2m x 2n), warp tile 64x64.
// B/MAC = 0.125: crossbar floor balanced against tensor floor.
// C[m,n] = op( sum_k A[m,k] * Bw[n,k] ),  N%128==0, K%32==0.
// OP: 0 none, 1 relu^2, 2 sigmoid, 3 resid+acc, 4 resid+gate*acc
// SMEM: 3-stage A[3][128][36] + B[3][128][36] floats.
#define LDS_STRIDE 36
#define BUF_FLOATS (128 * LDS_STRIDE)     // 4608
#define GEMM_SMEM  (6 * BUF_FLOATS * 4)   // 110592 B

template<int OP>
__device__ __forceinline__ void gemm_core(
    const float* __restrict__ A, const float* __restrict__ Bw, float* __restrict__ Cmat,
    const float* __restrict__ resid, const float* __restrict__ gate,
    int N, int K, int bm, int bn, float* smf)
{
    float* Asm = smf;                       // [3][4608]
    float* Bsm = smf + 3 * BUF_FLOATS;      // [3][4608]
    uint32_t sb = smem_u32(smf);

    int tid = threadIdx.x;                   // 0..127
    int lane = tid & 31, wid = tid >> 5;     // 4 warps
    int g = lane >> 2, t = lane & 3;         // groupID, thread-in-group
    int warp_m = wid >> 1, warp_n = wid & 1; // 2 x 2 warps
    int m0 = warp_m * 64, n0 = warp_n * 64;

    const float* Abase = A  + (size_t)bm * K;
    const float* Bbase = Bw + (size_t)bn * K;

    float acc[4][8][4];
    #pragma unroll
    for (int mi = 0; mi < 4; mi++)
        #pragma unroll
        for (int ni = 0; ni < 8; ni++)
            #pragma unroll
            for (int q = 0; q < 4; q++) acc[mi][ni][q] = 0.f;

    int nk = K >> 5;

    // stage `chunk` into smem slot chunk%3 (8 float4 per matrix per thread)
    auto stage = [&](int chunk) {
        int s = chunk - (chunk / 3) * 3;
        uint32_t asb = sb + (uint32_t)s * BUF_FLOATS * 4;
        uint32_t bsb = sb + (uint32_t)(3 + s) * BUF_FLOATS * 4;
        int k0 = chunk << 5;
        #pragma unroll
        for (int s4 = 0; s4 < 8; s4++) {
            int idx = tid + s4 * 128;
            int row = idx >> 3, c4 = idx & 7;   // 8 float4 per 32-float row
            uint32_t doff = (uint32_t)(row * LDS_STRIDE + c4 * 4) * 4;
            cp_async16(asb + doff, Abase + (size_t)row * K + k0 + c4 * 4);
            cp_async16(bsb + doff, Bbase + (size_t)row * K + k0 + c4 * 4);
        }
        CP_COMMIT();
    };

    stage(0);
    if (nk > 1) stage(1);

    for (int i = 0; i < nk; i++) {
        if (i + 2 < nk) { stage(i + 2); CP_WAIT2(); }
        else if (i + 1 < nk) { CP_WAIT1(); }
        else { CP_WAIT0(); }
        __syncthreads();

        int s = i - (i / 3) * 3;
        const float* As_ = Asm + s * BUF_FLOATS;
        const float* Bs_ = Bsm + s * BUF_FLOATS;

        #pragma unroll
        for (int ks = 0; ks < 4; ks++) {
            int k = ks * 8;
            uint32_t af[4][4], bf[8][2];
            #pragma unroll
            for (int mi = 0; mi < 4; mi++) {
                int base = (m0 + mi * 16 + g) * LDS_STRIDE + k + t;
                af[mi][0] = __float_as_uint(As_[base]);
                af[mi][1] = __float_as_uint(As_[base + 8 * LDS_STRIDE]);
                af[mi][2] = __float_as_uint(As_[base + 4]);
                af[mi][3] = __float_as_uint(As_[base + 8 * LDS_STRIDE + 4]);
            }
            #pragma unroll
            for (int ni = 0; ni < 8; ni++) {
                int base = (n0 + ni * 8 + g) * LDS_STRIDE + k + t;
                bf[ni][0] = __float_as_uint(Bs_[base]);
                bf[ni][1] = __float_as_uint(Bs_[base + 4]);
            }
            #pragma unroll
            for (int mi = 0; mi < 4; mi++)
                #pragma unroll
                for (int ni = 0; ni < 8; ni++)
                    mma_tf32(acc[mi][ni], af[mi], bf[ni]);
        }
        __syncthreads();
    }

    // ---- epilogue ----
    #pragma unroll
    for (int mi = 0; mi < 4; mi++) {
        #pragma unroll
        for (int half = 0; half < 2; half++) {
            int row = bm + m0 + mi * 16 + g + half * 8;
            #pragma unroll
            for (int ni = 0; ni < 8; ni++) {
                int col = bn + n0 + ni * 8 + t * 2;
                size_t o = (size_t)row * N + col;
                float c0 = acc[mi][ni][half * 2 + 0];
                float c1 = acc[mi][ni][half * 2 + 1];
                float v0, v1;
                if (OP == 1) {
                    float t0 = fmaxf(c0, 0.f), t1 = fmaxf(c1, 0.f);
                    v0 = t0 * t0; v1 = t1 * t1;
                } else if (OP == 2) {
                    v0 = 1.f / (1.f + expf(-c0)); v1 = 1.f / (1.f + expf(-c1));
                } else if (OP == 3) {
                    float2 rv = *(const float2*)&resid[o];
                    v0 = rv.x + c0; v1 = rv.y + c1;
                } else if (OP == 4) {
                    float2 rv = *(const float2*)&resid[o];
                    float2 gv = *(const float2*)&gate[o];
                    v0 = rv.x + gv.x * c0; v1 = rv.y + gv.y * c1;
                } else {
                    v0 = c0; v1 = c1;
                }
                float2 w2; w2.x = v0; w2.y = v1;
                *(float2*)&Cmat[o] = w2;
            }
        }
    }
}

template<int OP>
__global__ __launch_bounds__(128, 2) void gemm_tc(
    const float* __restrict__ A, const float* __restrict__ Bw, float* __restrict__ Cmat,
    const float* __restrict__ resid, const float* __restrict__ gate,
    int M, int N, int K)
{
    extern __shared__ __align__(16) float smf[];
    gemm_core<OP>(A, Bw, Cmat, resid, gate, N, K,
                  blockIdx.y * 128, blockIdx.x * 128, smf);
}

// z-batched k/v/r GEMM: one launch, blockIdx.z selects (A, W, C) triple
__global__ __launch_bounds__(128, 2) void gemm_kvr(
    const float* __restrict__ A0, const float* __restrict__ A1, const float* __restrict__ A2,
    const float* __restrict__ W0, const float* __restrict__ W1, const float* __restrict__ W2,
    float* __restrict__ C0, float* __restrict__ C1, float* __restrict__ C2,
    int N, int K)
{
    extern __shared__ __align__(16) float smf[];
    const float* A  = (blockIdx.z == 0) ? A0 : (blockIdx.z == 1) ? A1 : A2;
    const float* Bw = (blockIdx.z == 0) ? W0 : (blockIdx.z == 1) ? W1 : W2;
    float*       C  = (blockIdx.z == 0) ? C0 : (blockIdx.z == 1) ? C1 : C2;
    gemm_core<0>(A, Bw, C, nullptr, nullptr, N, K,
                 blockIdx.y * 128, blockIdx.x * 128, smf);
}

// merged FFN-up (relu^2) + rw (sigmoid) GEMMs: grid.x = 32 + 8
__global__ __launch_bounds__(128, 2) void gemm_up_rw(
    const float* __restrict__ xk, const float* __restrict__ fkw, float* __restrict__ kkout,
    const float* __restrict__ xr, const float* __restrict__ frw, float* __restrict__ sout,
    int K)
{
    extern __shared__ __align__(16) float smf[];
    int bx = blockIdx.x;
    if (bx < FFNq / 128) {
        gemm_core<1>(xk, fkw, kkout, nullptr, nullptr, FFNq, K,
                     blockIdx.y * 128, bx * 128, smf);
    } else {
        gemm_core<2>(xr, frw, sout, nullptr, nullptr, Cq, K,
                     blockIdx.y * 128, (bx - FFNq / 128) * 128, smf);
    }
}

// ======================= fused LN + token-shift mix =======================
__device__ __forceinline__ void ln_pair(
    const float* __restrict__ x, int row, int t, int tid,
    const float* __restrict__ w, const float* __restrict__ b,
    float4& h, float4& hp)
{
    float4 v = ((const float4*)(x + (size_t)row * Cq))[tid];
    float4 vp = make_float4(0.f, 0.f, 0.f, 0.f);
    if (t != 0) vp = ((const float4*)(x + (size_t)(row - 1) * Cq))[tid];
    float s   = v.x + v.y + v.z + v.w;
    float ss  = v.x*v.x + v.y*v.y + v.z*v.z + v.w*v.w;
    float sp  = vp.x + vp.y + vp.z + vp.w;
    float ssp = vp.x*vp.x + vp.y*vp.y + vp.z*vp.z + vp.w*vp.w;
    #pragma unroll
    for (int o = 16; o > 0; o >>= 1) {
        s   += __shfl_xor_sync(0xffffffffu, s, o);
        ss  += __shfl_xor_sync(0xffffffffu, ss, o);
        sp  += __shfl_xor_sync(0xffffffffu, sp, o);
        ssp += __shfl_xor_sync(0xffffffffu, ssp, o);
    }
    __shared__ float sm[4][8];
    int wid = tid >> 5, lane = tid & 31;
    if (lane == 0) { sm[0][wid] = s; sm[1][wid] = ss; sm[2][wid] = sp; sm[3][wid] = ssp; }
    __syncthreads();
    float st = 0.f, sst = 0.f, spt = 0.f, sspt = 0.f;
    #pragma unroll
    for (int i = 0; i < 8; i++) { st += sm[0][i]; sst += sm[1][i]; spt += sm[2][i]; sspt += sm[3][i]; }
    float mean  = st * (1.0f / Cq);
    float var   = sst * (1.0f / Cq) - mean * mean;
    float rstd  = rsqrtf(var + 1e-5f);
    float meanp = spt * (1.0f / Cq);
    float varp  = sspt * (1.0f / Cq) - meanp * meanp;
    float rstdp = rsqrtf(varp + 1e-5f);
    float4 wv = ((const float4*)w)[tid];
    float4 bv = ((const float4*)b)[tid];
    h.x = (v.x - mean) * rstd * wv.x + bv.x;
    h.y = (v.y - mean) * rstd * wv.y + bv.y;
    h.z = (v.z - mean) * rstd * wv.z + bv.z;
    h.w = (v.w - mean) * rstd * wv.w + bv.w;
    if (t != 0) {
        hp.x = (vp.x - meanp) * rstdp * wv.x + bv.x;
        hp.y = (vp.y - meanp) * rstdp * wv.y + bv.y;
        hp.z = (vp.z - meanp) * rstdp * wv.z + bv.z;
        hp.w = (vp.w - meanp) * rstdp * wv.w + bv.w;
    } else {
        hp = make_float4(0.f, 0.f, 0.f, 0.f);
    }
}

__global__ __launch_bounds__(256) void lnmix3_kernel(
    const float* __restrict__ x, const float* __restrict__ w, const float* __restrict__ b,
    const float* __restrict__ mk, const float* __restrict__ mv, const float* __restrict__ mr,
    float* __restrict__ xk, float* __restrict__ xv, float* __restrict__ xr)
{
    int row = blockIdx.x, t = row % Tq, tid = threadIdx.x;
    float4 h, hp;
    ln_pair(x, row, t, tid, w, b, h, hp);
    float4 k4 = ((const float4*)mk)[tid];
    float4 v4 = ((const float4*)mv)[tid];
    float4 r4 = ((const float4*)mr)[tid];
    float4 ok, ov, orr;
    ok.x  = hp.x + k4.x * (h.x - hp.x); ok.y  = hp.y + k4.y * (h.y - hp.y);
    ok.z  = hp.z + k4.z * (h.z - hp.z); ok.w  = hp.w + k4.w * (h.w - hp.w);
    ov.x  = hp.x + v4.x * (h.x - hp.x); ov.y  = hp.y + v4.y * (h.y - hp.y);
    ov.z  = hp.z + v4.z * (h.z - hp.z); ov.w  = hp.w + v4.w * (h.w - hp.w);
    orr.x = hp.x + r4.x * (h.x - hp.x); orr.y = hp.y + r4.y * (h.y - hp.y);
    orr.z = hp.z + r4.z * (h.z - hp.z); orr.w = hp.w + r4.w * (h.w - hp.w);
    ((float4*)(xk + (size_t)row * Cq))[tid] = ok;
    ((float4*)(xv + (size_t)row * Cq))[tid] = ov;
    ((float4*)(xr + (size_t)row * Cq))[tid] = orr;
}

__global__ __launch_bounds__(256) void lnmix2_kernel(
    const float* __restrict__ x, const float* __restrict__ w, const float* __restrict__ b,
    const float* __restrict__ mk, const float* __restrict__ mr,
    float* __restrict__ xk, float* __restrict__ xr)
{
    int row = blockIdx.x, t = row % Tq, tid = threadIdx.x;
    float4 h, hp;
    ln_pair(x, row, t, tid, w, b, h, hp);
    float4 k4 = ((const float4*)mk)[tid];
    float4 r4 = ((const float4*)mr)[tid];
    float4 ok, orr;
    ok.x  = hp.x + k4.x * (h.x - hp.x); ok.y  = hp.y + k4.y * (h.y - hp.y);
    ok.z  = hp.z + k4.z * (h.z - hp.z); ok.w  = hp.w + k4.w * (h.w - hp.w);
    orr.x = hp.x + r4.x * (h.x - hp.x); orr.y = hp.y + r4.y * (h.y - hp.y);
    orr.z = hp.z + r4.z * (h.z - hp.z); orr.w = hp.w + r4.w * (h.w - hp.w);
    ((float4*)(xk + (size_t)row * Cq))[tid] = ok;
    ((float4*)(xr + (size_t)row * Cq))[tid] = orr;
}

// ======================= WKV recurrence =======================
#define WSTEP 8
__device__ __forceinline__ void wkv_load8(
    const float* __restrict__ k, const float* __restrict__ v, const float* __restrict__ r,
    size_t base, int blk, float* kb, float* vb, float* rb)
{
    size_t o = base + (size_t)blk * WSTEP * Cq;
    #pragma unroll
    for (int j = 0; j < WSTEP; j++) {
        kb[j] = k[o]; vb[j] = v[o]; rb[j] = r[o];
        o += Cq;
    }
}
__device__ __forceinline__ void wkv_comp8(
    float* __restrict__ out, size_t base, int blk,
    const float* kb, const float* vb, const float* rb,
    float w, float u, float& aa, float& bb, float& pp)
{
    size_t o = base + (size_t)blk * WSTEP * Cq;
    #pragma unroll
    for (int j = 0; j < WSTEP; j++) {
        float kk = kb[j], vv = vb[j], rr = rb[j];
        float ww = u + kk;
        float p  = fmaxf(pp, ww);
        float e1 = expf(pp - p), e2 = expf(ww - p);
        float ov = (e1 * aa + e2 * vv) / (e1 * bb + e2);
        out[o] = ov * (1.f / (1.f + expf(-rr)));
        float ww2 = pp + w;
        float p2  = fmaxf(ww2, kk);
        float e1b = expf(ww2 - p2), e2b = expf(kk - p2);
        aa = e1b * aa + e2b * vv;
        bb = e1b * bb + e2b;
        pp = p2;
        o += Cq;
    }
}

__global__ __launch_bounds__(128) void wkv_kernel(
    const float* __restrict__ k, const float* __restrict__ v, const float* __restrict__ r,
    const float* __restrict__ decay, const float* __restrict__ first,
    float* __restrict__ out)
{
    int idx = blockIdx.x * blockDim.x + threadIdx.x;   // 0 .. B*C-1
    int b = idx / Cq, c = idx % Cq;
    float w = -expf(decay[c]);
    float u = first[c];
    float aa = 0.f, bb = 0.f, pp = -1e38f;
    size_t base = (size_t)b * Tq * Cq + c;

    const int NB = Tq / WSTEP;     // 256 (even)
    float kb0[WSTEP], vb0[WSTEP], rb0[WSTEP];
    float kb1[WSTEP], vb1[WSTEP], rb1[WSTEP];
    wkv_load8(k, v, r, base, 0, kb0, vb0, rb0);
    for (int blk = 0; blk < NB; blk += 2) {
        wkv_load8(k, v, r, base, blk + 1, kb1, vb1, rb1);
        wkv_comp8(out, base, blk, kb0, vb0, rb0, w, u, aa, bb, pp);
        if (blk + 2 < NB) wkv_load8(k, v, r, base, blk + 2, kb0, vb0, rb0);
        wkv_comp8(out, base, blk + 1, kb1, vb1, rb1, w, u, aa, bb, pp);
    }
}

// ======================= host orchestration =======================
extern "C" void kernel_launch(void* const* d_in, const int* in_sizes, int n_in,
                              void* d_out, int out_size)
{
    const float* x          = (const float*)d_in[0];
    const float* ln1_w      = (const float*)d_in[1];
    const float* ln1_b      = (const float*)d_in[2];
    const float* ln2_w      = (const float*)d_in[3];
    const float* ln2_b      = (const float*)d_in[4];
    const float* time_decay = (const float*)d_in[5];
    const float* time_first = (const float*)d_in[6];
    const float* tmk        = (const float*)d_in[7];
    const float* tmv        = (const float*)d_in[8];
    const float* tmr        = (const float*)d_in[9];
    const float* att_kw     = (const float*)d_in[10];
    const float* att_vw     = (const float*)d_in[11];
    const float* att_rw     = (const float*)d_in[12];
    const float* att_ow     = (const float*)d_in[13];
    const float* f_tmk      = (const float*)d_in[14];
    const float* f_tmr      = (const float*)d_in[15];
    const float* f_kw       = (const float*)d_in[16];
    const float* f_rw       = (const float*)d_in[17];
    const float* f_vw       = (const float*)d_in[18];
    float* out = (float*)d_out;

    float* pool = nullptr;
    cudaGetSymbolAddress((void**)&pool, g_pool);
    float* b1 = pool + 1 * (size_t)MCq;
    float* b2 = pool + 2 * (size_t)MCq;
    float* b3 = pool + 3 * (size_t)MCq;
    float* b4 = pool + 4 * (size_t)MCq;
    float* b5 = pool + 5 * (size_t)MCq;
    float* b6 = pool + 6 * (size_t)MCq;
    float* bf = pool + 7 * (size_t)MCq;   // [M, FFN]

    cudaFuncSetAttribute(gemm_tc<3>, cudaFuncAttributeMaxDynamicSharedMemorySize, GEMM_SMEM);
    cudaFuncSetAttribute(gemm_tc<4>, cudaFuncAttributeMaxDynamicSharedMemorySize, GEMM_SMEM);
    cudaFuncSetAttribute(gemm_kvr,   cudaFuncAttributeMaxDynamicSharedMemorySize, GEMM_SMEM);
    cudaFuncSetAttribute(gemm_up_rw, cudaFuncAttributeMaxDynamicSharedMemorySize, GEMM_SMEM);

    dim3 gC(Cq / 128, Mq / 128);            // (8, 64)
    dim3 gKVR(Cq / 128, Mq / 128, 3);       // (8, 64, 3)
    dim3 gUPRW(FFNq / 128 + Cq / 128, Mq / 128);  // (40, 64)

    // ---- TimeMix ----
    lnmix3_kernel<<<Mq, 256>>>(x, ln1_w, ln1_b, tmk, tmv, tmr, b1, b2, b3);
    gemm_kvr<<<gKVR, 128, GEMM_SMEM>>>(b1, b2, b3, att_kw, att_vw, att_rw,
                                       b4, b5, b6, Cq, Cq);
    wkv_kernel<<<(Bq * Cq) / 128, 128>>>(b4, b5, b6, time_decay, time_first, b1);
    gemm_tc<3><<<gC, 128, GEMM_SMEM>>>(b1, att_ow, b2, x, nullptr, Mq, Cq, Cq);   // y = x + rwkv@ow

    // ---- ChannelMix ----
    lnmix2_kernel<<<Mq, 256>>>(b2, ln2_w, ln2_b, f_tmk, f_tmr, b3, b4);
    gemm_up_rw<<<gUPRW, 128, GEMM_SMEM>>>(b3, f_kw, bf, b4, f_rw, b5, Cq);        // relu^2 + sigmoid
    gemm_tc<4><<<gC, 128, GEMM_SMEM>>>(bf, f_vw, out, b2, b5, Mq, Cq, FFNq);      // y + s*(kk@vw)
}